// round 14
// baseline (speedup 1.0000x reference)
#include <cuda_runtime.h>
#include <cuda_fp16.h>
#include <cstdint>

#define NEXP 2048
#define NDICT 65536
#define NPIX 1600
#define ROWB 3200              // NPIX * 2 bytes per f16 row (exactly 25x128B)
#define KTOP 10
#define NCAND 32
#define BM 128
#define BN 128
#define NST 25                 // k-stages of 64 f16 values (128B per row)
#define NTILE (NDICT / BN)     // 512 candidate tiles per row
#define STAGE_BYTES 32768      // A:128*128B + B:128*128B
#define SMEM_DYN (3 * STAGE_BYTES)

typedef unsigned long long u64;

__device__ __half g_Qs[(size_t)NEXP * NPIX];   // hi-f16, row-major
__device__ __half g_Ps[(size_t)NDICT * NPIX];
__device__ float g_mq[NEXP], g_iq[NEXP], g_md[NDICT], g_id[NDICT];
__device__ u64 g_cand[(size_t)NEXP * NTILE * KTOP];   // 84 MB
__device__ int g_top32[(size_t)NEXP * NCAND];

__device__ __forceinline__ uint32_t s2u(const void* p) {
    uint32_t a;
    asm("{ .reg .u64 t; cvta.to.shared.u64 t, %1; cvt.u32.u64 %0, t; }" : "=r"(a) : "l"(p));
    return a;
}
#define LDSM4(r, addr) asm volatile( \
    "ldmatrix.sync.aligned.m8n8.x4.shared.b16 {%0,%1,%2,%3}, [%4];" \
    : "=r"((r)[0]), "=r"((r)[1]), "=r"((r)[2]), "=r"((r)[3]) : "r"(addr))
// f16 accumulate: D/C are 2x f16x2 regs
#define MMAH(d, a, b0, b1) asm volatile( \
    "mma.sync.aligned.m16n8k16.row.col.f16.f16.f16.f16 " \
    "{%0,%1},{%2,%3,%4,%5},{%6,%7},{%0,%1};" \
    : "+r"((d)[0]), "+r"((d)[1]) \
    : "r"((a)[0]), "r"((a)[1]), "r"((a)[2]), "r"((a)[3]), "r"(b0), "r"(b1))
#define CPA16(dst, src) asm volatile( \
    "cp.async.cg.shared.global [%0], [%1], 16;" :: "r"(dst), "l"(src) : "memory")

__device__ __forceinline__ u64 pack_vi(float v, int idx) {
    uint32_t ub = __float_as_uint(v);
    ub = (ub & 0x80000000u) ? ~ub : (ub | 0x80000000u);
    return ((u64)ub << 32) | (uint32_t)(~(uint32_t)idx);
}
__device__ __forceinline__ void ins10(u64* top, u64 p) {
    if (p > top[KTOP - 1]) {
#pragma unroll
        for (int q = KTOP - 1; q >= 1; q--)
            if (top[q - 1] < p) top[q] = top[q - 1];
        bool placed = false;
#pragma unroll
        for (int q = 0; q < KTOP; q++)
            if (!placed && top[q] < p) { top[q] = p; placed = true; }
    }
}

// fp32 -> hi-f16 + row stats. Per-row stats arithmetic is bitwise identical
// to the R1 rowstats kernel (same loop/shuffle/final-sum).
__global__ void __launch_bounds__(512, 2)
convert_kernel(const float* __restrict__ X, int which, int rbase) {
    const int half = threadIdx.x >> 8, tid = threadIdx.x & 255;
    const int row = rbase + blockIdx.x * 2 + half;
    const float* x = X + (size_t)row * NPIX;
    __half* o = (which ? g_Ps : g_Qs) + (size_t)row * NPIX;
    float s = 0.f, s2 = 0.f;
    for (int i = tid; i < NPIX; i += 256) {
        float f = x[i];
        s += f; s2 += f * f;
        o[i] = __float2half_rn(f);
    }
#pragma unroll
    for (int off = 16; off > 0; off >>= 1) {
        s  += __shfl_down_sync(0xffffffffu, s, off);
        s2 += __shfl_down_sync(0xffffffffu, s2, off);
    }
    __shared__ float sh_s[2][8], sh_s2[2][8];
    int w = tid >> 5, l = tid & 31;
    if (l == 0) { sh_s[half][w] = s; sh_s2[half][w] = s2; }
    __syncthreads();
    if (tid == 0) {
        float ts = 0.f, ts2 = 0.f;
#pragma unroll
        for (int i = 0; i < 8; i++) { ts += sh_s[half][i]; ts2 += sh_s2[half][i]; }
        float m = ts / (float)NPIX;
        float inv = rsqrtf(ts2 - m * ts);
        if (which) { g_md[row] = m; g_id[row] = inv; }
        else       { g_mq[row] = m; g_iq[row] = inv; }
    }
}

// 1-term hi-f16 selection GEMM, f16 ACCUMULATE (testing full-rate HMMA).
// CTA 128x128, 256 threads, 8 warps of 32x64, 3-stage cp.async, 2 CTAs/SM.
__global__ void __launch_bounds__(256, 2) gemm_kernel() {
    extern __shared__ uint8_t dsm[];
    __shared__ float2 s_nd[BN];

    const int tid = threadIdx.x, lane = tid & 31, wid = tid >> 5;
    const int wm = wid & 3, wn = wid >> 2;       // 4 x 2 warps of 32x64
    const int m_base = blockIdx.x * BM, n_base = blockIdx.y * BN;
    const uint32_t sbase = s2u(dsm);

    // ---- producer constants: 8 x 16B cp.async per thread per stage ----
    const int r0 = tid >> 3;
    const uint32_t s8 = (uint32_t)(tid & 7);
    const uint32_t sw = ((uint32_t)(r0 & 7)) << 4;   // row&7 invariant over jj
    const uint32_t dst0 = (uint32_t)r0 * 128u + ((s8 * 16u) ^ sw);
    const char* srcA0 = (const char*)g_Qs + (size_t)(m_base + r0) * ROWB + s8 * 16u;
    const char* srcB0 = (const char*)g_Ps + (size_t)(n_base + r0) * ROWB + s8 * 16u;

    // ---- ldmatrix lane constants (SW128) ----
    const uint32_t xorL  = (uint32_t)(lane & 7) << 4;
    const uint32_t halfA = (uint32_t)(lane >> 4) << 4;
    const uint32_t halfB = (uint32_t)((lane >> 3) & 1) << 4;
    const uint32_t aoff0 = (uint32_t)(32 * wm + (lane & 15)) * 128u;
    const uint32_t aoff1 = aoff0 + 16 * 128u;
    uint32_t boff[4];
#pragma unroll
    for (int j = 0; j < 4; j++)
        boff[j] = 16384u + (uint32_t)(64 * wn + 16 * j + (lane & 7) + 8 * ((lane >> 4) & 1)) * 128u;

    uint32_t acc[2][8][2];   // f16x2 accumulators
#pragma unroll
    for (int i = 0; i < 2; i++)
#pragma unroll
        for (int j = 0; j < 8; j++) { acc[i][j][0] = 0u; acc[i][j][1] = 0u; }

    // ---- prologue: stages 0,1 ----
#pragma unroll
    for (int p = 0; p < 2; p++) {
        const uint32_t sb = sbase + p * STAGE_BYTES;
#pragma unroll
        for (int jj = 0; jj < 4; jj++) {
            CPA16(sb + dst0 + 4096u * jj, srcA0 + (size_t)p * 128 + (size_t)jj * (32 * ROWB));
            CPA16(sb + 16384u + dst0 + 4096u * jj,
                  srcB0 + (size_t)p * 128 + (size_t)jj * (32 * ROWB));
        }
        asm volatile("cp.async.commit_group;" ::: "memory");
    }

    for (int t = 0; t < NST; t++) {
        asm volatile("cp.async.wait_group 1;" ::: "memory");
        __syncthreads();
        if (t + 2 < NST) {
            const uint32_t sb = sbase + ((t + 2) % 3) * STAGE_BYTES;
            const size_t ko = (size_t)(t + 2) * 128;
#pragma unroll
            for (int jj = 0; jj < 4; jj++) {
                CPA16(sb + dst0 + 4096u * jj, srcA0 + ko + (size_t)jj * (32 * ROWB));
                CPA16(sb + 16384u + dst0 + 4096u * jj, srcB0 + ko + (size_t)jj * (32 * ROWB));
            }
        }
        asm volatile("cp.async.commit_group;" ::: "memory");

        const uint32_t sb = sbase + (t % 3) * STAGE_BYTES;
#pragma unroll
        for (int s = 0; s < 4; s++) {          // 4 k16-steps per 128B stage
            const uint32_t sk = 32u * s;
            const uint32_t lowA = (sk | halfA) ^ xorL;
            const uint32_t lowB = (sk | halfB) ^ xorL;
            uint32_t a0[4], a1[4];
            LDSM4(a0, sb + aoff0 + lowA);
            LDSM4(a1, sb + aoff1 + lowA);
#pragma unroll
            for (int j = 0; j < 4; j++) {
                uint32_t b[4];
                LDSM4(b, sb + boff[j] + lowB);
                MMAH(acc[0][2 * j],     a0, b[0], b[1]);
                MMAH(acc[0][2 * j + 1], a0, b[2], b[3]);
                MMAH(acc[1][2 * j],     a1, b[0], b[1]);
                MMAH(acc[1][2 * j + 1], a1, b[2], b[3]);
            }
        }
    }
    __syncthreads();

    // ---- epilogue: convert f16 acc -> f32, dump to smem (128x136 = 70KB) ----
    float* cbuf = (float*)dsm;
#pragma unroll
    for (int mi = 0; mi < 2; mi++)
#pragma unroll
        for (int nf = 0; nf < 8; nf++) {
            int r = 32 * wm + 16 * mi + (lane >> 2);
            int c = 64 * wn + 8 * nf + 2 * (lane & 3);
            __half2 h0 = *reinterpret_cast<__half2*>(&acc[mi][nf][0]);
            __half2 h1 = *reinterpret_cast<__half2*>(&acc[mi][nf][1]);
            float2 f0 = __half22float2(h0);
            float2 f1 = __half22float2(h1);
            cbuf[r * 136 + c]           = f0.x;
            cbuf[r * 136 + c + 1]       = f0.y;
            cbuf[(r + 8) * 136 + c]     = f1.x;
            cbuf[(r + 8) * 136 + c + 1] = f1.y;
        }
    if (tid < BN) {
        int n = n_base + tid;
        float idv = g_id[n];
        s_nd[tid] = make_float2(idv, g_md[n] * idv);
    }
    __syncthreads();

    // ---- per (row, 64-col chunk) top-10 ----
    const int row = tid >> 1, chunk = tid & 1;
    const int grow = m_base + row;
    const float iqv = g_iq[grow];
    const float cmq = (float)NPIX * g_mq[grow];
    u64 top[KTOP];
#pragma unroll
    for (int i = 0; i < KTOP; i++) top[i] = 0ULL;

    const int cb = 64 * chunk;
#pragma unroll 8
    for (int jj = 0; jj < 64; jj++) {
        int col = cb + jj;
        float2 nd = s_nd[col];
        float v = (cbuf[row * 136 + col] * nd.x - cmq * nd.y) * iqv;
        ins10(top, pack_vi(v, n_base + col));
    }
    __syncthreads();   // all cbuf reads done; reuse smem for candidates

    u64* csm = (u64*)dsm;   // [256][KTOP] = 20 KB
#pragma unroll
    for (int i = 0; i < KTOP; i++) csm[tid * KTOP + i] = top[i];
    __syncthreads();

    // ---- 2->1 chunk merge per row, write one top-10 list per (row, tile) ----
    if (tid < BM) {
        u64 mtop[KTOP];
#pragma unroll
        for (int i = 0; i < KTOP; i++) mtop[i] = 0ULL;
        const u64* base = csm + (size_t)tid * 2 * KTOP;
        for (int c = 0; c < 2 * KTOP; c++) ins10(mtop, base[c]);
        u64* dst = g_cand + ((size_t)(m_base + tid) * NTILE + blockIdx.y) * KTOP;
#pragma unroll
        for (int i = 0; i < KTOP; i++) dst[i] = mtop[i];
    }
}

// Merge 512 tile-lists per row -> top-32 candidate INDICES (selection only).
__global__ void merge32_kernel() {
    const int row = blockIdx.x, tid = threadIdx.x;  // 256 threads
    __shared__ u64 c[256 * KTOP];
    __shared__ u64 red[256];

    u64 top[KTOP];
#pragma unroll
    for (int i = 0; i < KTOP; i++) top[i] = 0ULL;
    const u64* src = g_cand + ((size_t)row * NTILE + (size_t)tid * 2) * KTOP;
    for (int j = 0; j < 2 * KTOP; j++) ins10(top, src[j]);
#pragma unroll
    for (int j = 0; j < KTOP; j++) c[tid * KTOP + j] = top[j];  // sorted desc
    int cur = 0;
    __syncthreads();

    for (int r = 0; r < NCAND; r++) {
        u64 v = (cur < KTOP) ? c[tid * KTOP + cur] : 0ULL;
        red[tid] = v;
        __syncthreads();
        for (int s = 128; s > 0; s >>= 1) {
            if (tid < s && red[tid + s] > red[tid]) red[tid] = red[tid + s];
            __syncthreads();
        }
        u64 w = red[0];
        if (v == w && cur < KTOP) cur++;
        if (tid == 0)
            g_top32[(size_t)row * NCAND + r] = (int)(~(uint32_t)(w & 0xffffffffu));
        __syncthreads();
    }
}

// EXACT rescore (bitwise-replicates the R1 kernel's accumulation order):
// one thread per candidate, single fp32 fmaf chain over k ascending on RAW
// inputs + R1's exact epilogue. Reproduces reference-observed ordering.
__global__ void __launch_bounds__(256, 4)
rescore_kernel(const float* __restrict__ Q, const float* __restrict__ P,
               const float* __restrict__ so3, float* __restrict__ out) {
    const int tid = threadIdx.x;
    const int rloc = tid >> 5, cand = tid & 31;   // 8 rows x 32 cands per block
    const int row = blockIdx.x * 8 + rloc;
    const int idx = g_top32[(size_t)row * NCAND + cand];

    const float* q = Q + (size_t)row * NPIX;
    const float* p = P + (size_t)idx * NPIX;
    float acc = 0.f;
#pragma unroll 8
    for (int k = 0; k < NPIX; k++)
        acc = fmaf(q[k], p[k], acc);

    float corr = (float)NPIX * g_mq[row];
    float v = (acc - corr * g_md[idx]) * g_iq[row] * g_id[idx];

    __shared__ u64 sp[256];
    sp[tid] = pack_vi(v, idx);
    __syncthreads();

    u64 mine = sp[tid];
    int rank = 0;
#pragma unroll
    for (int j = 0; j < NCAND; j++) rank += (sp[rloc * 32 + j] > mine);
    if (rank < KTOP) {
        float cc = fminf(fmaxf(v, -1.0f), 1.0f);
        out[(size_t)row * KTOP + rank] = acosf(cc);
        out[(size_t)NEXP * KTOP + (size_t)row * KTOP + rank] = (float)idx;
        const float* qt = so3 + (size_t)idx * 4;
        float* od = out + 2 * (size_t)NEXP * KTOP + ((size_t)row * KTOP + rank) * 4;
        od[0] = qt[0]; od[1] = qt[1]; od[2] = qt[2]; od[3] = qt[3];
    }
}

extern "C" void kernel_launch(void* const* d_in, const int* in_sizes, int n_in,
                              void* d_out, int out_size) {
    const float* Q   = (const float*)d_in[0];
    const float* P   = (const float*)d_in[1];
    const float* SO3 = (const float*)d_in[2];
    float* out = (float*)d_out;

    cudaFuncSetAttribute(gemm_kernel, cudaFuncAttributeMaxDynamicSharedMemorySize, SMEM_DYN);

    // gemm sits in the 4th (ncu-captured) launch slot.
    convert_kernel<<<NEXP / 2, 512>>>(Q, 0, 0);
    convert_kernel<<<NDICT / 4, 512>>>(P, 1, 0);
    convert_kernel<<<NDICT / 4, 512>>>(P, 1, NDICT / 2);

    dim3 grid(NEXP / BM, NDICT / BN);  // (16, 512)
    gemm_kernel<<<grid, 256, SMEM_DYN>>>();

    merge32_kernel<<<NEXP, 256>>>();
    rescore_kernel<<<NEXP / 8, 256>>>(Q, P, SO3, out);
}

// round 15
// speedup vs baseline: 1.1108x; 1.1108x over previous
#include <cuda_runtime.h>
#include <cuda_fp16.h>
#include <cstdint>

#define NEXP 2048
#define NDICT 65536
#define NPIX 1600
#define ROWB 3200              // NPIX * 2 bytes per f16 row == exactly 25x128B
#define KTOP 10
#define NCAND 16
#define BM 128
#define BN 128
#define NST 25                 // k-stages of 64 f16 values (128B per row), no padding
#define NTILE (NDICT / BN)     // 512 candidate tiles per row
#define STAGE_BYTES 32768      // A:128*128B + B:128*128B
#define SMEM_DYN (3 * STAGE_BYTES)

typedef unsigned long long u64;

__device__ __half g_Qs[(size_t)NEXP * NPIX];   // hi-f16, row-major (unpadded)
__device__ __half g_Ps[(size_t)NDICT * NPIX];
__device__ float g_mq[NEXP], g_iq[NEXP], g_md[NDICT], g_id[NDICT];
__device__ u64 g_cand[(size_t)NEXP * NTILE * KTOP];   // 84 MB
__device__ int g_top16[(size_t)NEXP * NCAND];

__device__ __forceinline__ uint32_t s2u(const void* p) {
    uint32_t a;
    asm("{ .reg .u64 t; cvta.to.shared.u64 t, %1; cvt.u32.u64 %0, t; }" : "=r"(a) : "l"(p));
    return a;
}
#define LDSM4(r, addr) asm volatile( \
    "ldmatrix.sync.aligned.m8n8.x4.shared.b16 {%0,%1,%2,%3}, [%4];" \
    : "=r"((r)[0]), "=r"((r)[1]), "=r"((r)[2]), "=r"((r)[3]) : "r"(addr))
#define MMA(d, a, b0, b1) asm volatile( \
    "mma.sync.aligned.m16n8k16.row.col.f32.f16.f16.f32 " \
    "{%0,%1,%2,%3},{%4,%5,%6,%7},{%8,%9},{%0,%1,%2,%3};" \
    : "+f"((d)[0]), "+f"((d)[1]), "+f"((d)[2]), "+f"((d)[3]) \
    : "r"((a)[0]), "r"((a)[1]), "r"((a)[2]), "r"((a)[3]), "r"(b0), "r"(b1))
#define CPA16(dst, src) asm volatile( \
    "cp.async.cg.shared.global [%0], [%1], 16;" :: "r"(dst), "l"(src) : "memory")

__device__ __forceinline__ u64 pack_vi(float v, int idx) {
    uint32_t ub = __float_as_uint(v);
    ub = (ub & 0x80000000u) ? ~ub : (ub | 0x80000000u);
    return ((u64)ub << 32) | (uint32_t)(~(uint32_t)idx);
}
__device__ __forceinline__ void ins10(u64* top, u64 p) {
    if (p > top[KTOP - 1]) {
#pragma unroll
        for (int q = KTOP - 1; q >= 1; q--)
            if (top[q - 1] < p) top[q] = top[q - 1];
        bool placed = false;
#pragma unroll
        for (int q = 0; q < KTOP; q++)
            if (!placed && top[q] < p) { top[q] = p; placed = true; }
    }
}

// fp32 -> hi-f16 + row stats. Per-row stats arithmetic is bitwise identical
// to the R1 rowstats kernel (same loop/shuffle/final-sum).
__global__ void __launch_bounds__(512, 2)
convert_kernel(const float* __restrict__ X, int which, int rbase) {
    const int half = threadIdx.x >> 8, tid = threadIdx.x & 255;
    const int row = rbase + blockIdx.x * 2 + half;
    const float* x = X + (size_t)row * NPIX;
    __half* o = (which ? g_Ps : g_Qs) + (size_t)row * NPIX;
    float s = 0.f, s2 = 0.f;
    for (int i = tid; i < NPIX; i += 256) {
        float f = x[i];
        s += f; s2 += f * f;
        o[i] = __float2half_rn(f);
    }
#pragma unroll
    for (int off = 16; off > 0; off >>= 1) {
        s  += __shfl_down_sync(0xffffffffu, s, off);
        s2 += __shfl_down_sync(0xffffffffu, s2, off);
    }
    __shared__ float sh_s[2][8], sh_s2[2][8];
    int w = tid >> 5, l = tid & 31;
    if (l == 0) { sh_s[half][w] = s; sh_s2[half][w] = s2; }
    __syncthreads();
    if (tid == 0) {
        float ts = 0.f, ts2 = 0.f;
#pragma unroll
        for (int i = 0; i < 8; i++) { ts += sh_s[half][i]; ts2 += sh_s2[half][i]; }
        float m = ts / (float)NPIX;
        float inv = rsqrtf(ts2 - m * ts);
        if (which) { g_md[row] = m; g_id[row] = inv; }
        else       { g_mq[row] = m; g_iq[row] = inv; }
    }
}

// 1-term hi-f16 selection GEMM (R10 winner config, unpadded K).
// CTA 128x128, 256 threads, 8 warps of 32x64, 3-stage cp.async, 2 CTAs/SM.
__global__ void __launch_bounds__(256, 2) gemm_kernel() {
    extern __shared__ uint8_t dsm[];
    __shared__ float2 s_nd[BN];

    const int tid = threadIdx.x, lane = tid & 31, wid = tid >> 5;
    const int wm = wid & 3, wn = wid >> 2;       // 4 x 2 warps of 32x64
    const int m_base = blockIdx.x * BM, n_base = blockIdx.y * BN;
    const uint32_t sbase = s2u(dsm);

    // ---- producer constants: 8 x 16B cp.async per thread per stage ----
    const int r0 = tid >> 3;
    const uint32_t s8 = (uint32_t)(tid & 7);
    const uint32_t sw = ((uint32_t)(r0 & 7)) << 4;   // row&7 invariant over jj
    const uint32_t dst0 = (uint32_t)r0 * 128u + ((s8 * 16u) ^ sw);
    const char* srcA0 = (const char*)g_Qs + (size_t)(m_base + r0) * ROWB + s8 * 16u;
    const char* srcB0 = (const char*)g_Ps + (size_t)(n_base + r0) * ROWB + s8 * 16u;

    // ---- ldmatrix lane constants (SW128) ----
    const uint32_t xorL  = (uint32_t)(lane & 7) << 4;
    const uint32_t halfA = (uint32_t)(lane >> 4) << 4;
    const uint32_t halfB = (uint32_t)((lane >> 3) & 1) << 4;
    const uint32_t aoff0 = (uint32_t)(32 * wm + (lane & 15)) * 128u;
    const uint32_t aoff1 = aoff0 + 16 * 128u;
    uint32_t boff[4];
#pragma unroll
    for (int j = 0; j < 4; j++)
        boff[j] = 16384u + (uint32_t)(64 * wn + 16 * j + (lane & 7) + 8 * ((lane >> 4) & 1)) * 128u;

    float acc[2][8][4];
#pragma unroll
    for (int i = 0; i < 2; i++)
#pragma unroll
        for (int j = 0; j < 8; j++)
#pragma unroll
            for (int k = 0; k < 4; k++) acc[i][j][k] = 0.f;

    // ---- prologue: stages 0,1 ----
#pragma unroll
    for (int p = 0; p < 2; p++) {
        const uint32_t sb = sbase + p * STAGE_BYTES;
#pragma unroll
        for (int jj = 0; jj < 4; jj++) {
            CPA16(sb + dst0 + 4096u * jj, srcA0 + (size_t)p * 128 + (size_t)jj * (32 * ROWB));
            CPA16(sb + 16384u + dst0 + 4096u * jj,
                  srcB0 + (size_t)p * 128 + (size_t)jj * (32 * ROWB));
        }
        asm volatile("cp.async.commit_group;" ::: "memory");
    }

    for (int t = 0; t < NST; t++) {
        asm volatile("cp.async.wait_group 1;" ::: "memory");
        __syncthreads();
        if (t + 2 < NST) {
            const uint32_t sb = sbase + ((t + 2) % 3) * STAGE_BYTES;
            const size_t ko = (size_t)(t + 2) * 128;
#pragma unroll
            for (int jj = 0; jj < 4; jj++) {
                CPA16(sb + dst0 + 4096u * jj, srcA0 + ko + (size_t)jj * (32 * ROWB));
                CPA16(sb + 16384u + dst0 + 4096u * jj, srcB0 + ko + (size_t)jj * (32 * ROWB));
            }
        }
        asm volatile("cp.async.commit_group;" ::: "memory");

        const uint32_t sb = sbase + (t % 3) * STAGE_BYTES;
#pragma unroll
        for (int s = 0; s < 4; s++) {          // 4 k16-steps per 128B stage
            const uint32_t sk = 32u * s;
            const uint32_t lowA = (sk | halfA) ^ xorL;
            const uint32_t lowB = (sk | halfB) ^ xorL;
            uint32_t a0[4], a1[4];
            LDSM4(a0, sb + aoff0 + lowA);
            LDSM4(a1, sb + aoff1 + lowA);
#pragma unroll
            for (int j = 0; j < 4; j++) {
                uint32_t b[4];
                LDSM4(b, sb + boff[j] + lowB);
                MMA(acc[0][2 * j],     a0, b[0], b[1]);
                MMA(acc[0][2 * j + 1], a0, b[2], b[3]);
                MMA(acc[1][2 * j],     a1, b[0], b[1]);
                MMA(acc[1][2 * j + 1], a1, b[2], b[3]);
            }
        }
    }
    __syncthreads();

    // ---- epilogue: dump C tile to smem (128 x 136 f32 = 70KB) ----
    float* cbuf = (float*)dsm;
#pragma unroll
    for (int mi = 0; mi < 2; mi++)
#pragma unroll
        for (int nf = 0; nf < 8; nf++) {
            int r = 32 * wm + 16 * mi + (lane >> 2);
            int c = 64 * wn + 8 * nf + 2 * (lane & 3);
            cbuf[r * 136 + c]           = acc[mi][nf][0];
            cbuf[r * 136 + c + 1]       = acc[mi][nf][1];
            cbuf[(r + 8) * 136 + c]     = acc[mi][nf][2];
            cbuf[(r + 8) * 136 + c + 1] = acc[mi][nf][3];
        }
    if (tid < BN) {
        int n = n_base + tid;
        float idv = g_id[n];
        s_nd[tid] = make_float2(idv, g_md[n] * idv);
    }
    __syncthreads();

    // ---- per (row, 64-col chunk) top-10 ----
    const int row = tid >> 1, chunk = tid & 1;
    const int grow = m_base + row;
    const float iqv = g_iq[grow];
    const float cmq = (float)NPIX * g_mq[grow];
    u64 top[KTOP];
#pragma unroll
    for (int i = 0; i < KTOP; i++) top[i] = 0ULL;

    const int cb = 64 * chunk;
#pragma unroll 8
    for (int jj = 0; jj < 64; jj++) {
        int col = cb + jj;
        float2 nd = s_nd[col];
        float v = (cbuf[row * 136 + col] * nd.x - cmq * nd.y) * iqv;
        ins10(top, pack_vi(v, n_base + col));
    }
    __syncthreads();   // all cbuf reads done; reuse smem for candidates

    u64* csm = (u64*)dsm;   // [256][KTOP] = 20 KB
#pragma unroll
    for (int i = 0; i < KTOP; i++) csm[tid * KTOP + i] = top[i];
    __syncthreads();

    // ---- 2->1 chunk merge per row, write one top-10 list per (row, tile) ----
    if (tid < BM) {
        u64 mtop[KTOP];
#pragma unroll
        for (int i = 0; i < KTOP; i++) mtop[i] = 0ULL;
        const u64* base = csm + (size_t)tid * 2 * KTOP;
        for (int c = 0; c < 2 * KTOP; c++) ins10(mtop, base[c]);
        u64* dst = g_cand + ((size_t)(m_base + tid) * NTILE + blockIdx.y) * KTOP;
#pragma unroll
        for (int i = 0; i < KTOP; i++) dst[i] = mtop[i];
    }
}

// Merge 512 tile-lists per row -> top-16 candidate INDICES (selection only).
__global__ void merge16_kernel() {
    const int row = blockIdx.x, tid = threadIdx.x;  // 256 threads
    __shared__ u64 c[256 * KTOP];
    __shared__ u64 red[256];

    u64 top[KTOP];
#pragma unroll
    for (int i = 0; i < KTOP; i++) top[i] = 0ULL;
    const u64* src = g_cand + ((size_t)row * NTILE + (size_t)tid * 2) * KTOP;
    for (int j = 0; j < 2 * KTOP; j++) ins10(top, src[j]);
#pragma unroll
    for (int j = 0; j < KTOP; j++) c[tid * KTOP + j] = top[j];  // sorted desc
    int cur = 0;
    __syncthreads();

    for (int r = 0; r < NCAND; r++) {
        u64 v = (cur < KTOP) ? c[tid * KTOP + cur] : 0ULL;
        red[tid] = v;
        __syncthreads();
        for (int s = 128; s > 0; s >>= 1) {
            if (tid < s && red[tid + s] > red[tid]) red[tid] = red[tid + s];
            __syncthreads();
        }
        u64 w = red[0];
        if (v == w && cur < KTOP) cur++;
        if (tid == 0)
            g_top16[(size_t)row * NCAND + r] = (int)(~(uint32_t)(w & 0xffffffffu));
        __syncthreads();
    }
}

// EXACT rescore (bitwise-replicates the R1 kernel's accumulation order):
// one thread per candidate, single fp32 fmaf chain over k ascending on RAW
// inputs + R1's exact epilogue. Reproduces reference-observed ordering.
__global__ void __launch_bounds__(256, 4)
rescore_kernel(const float* __restrict__ Q, const float* __restrict__ P,
               const float* __restrict__ so3, float* __restrict__ out) {
    const int tid = threadIdx.x;
    const int rloc = tid >> 4, cand = tid & 15;
    const int row = blockIdx.x * 16 + rloc;
    const int idx = g_top16[(size_t)row * NCAND + cand];

    const float* q = Q + (size_t)row * NPIX;
    const float* p = P + (size_t)idx * NPIX;
    float acc = 0.f;
#pragma unroll 8
    for (int k = 0; k < NPIX; k++)
        acc = fmaf(q[k], p[k], acc);

    float corr = (float)NPIX * g_mq[row];
    float v = (acc - corr * g_md[idx]) * g_iq[row] * g_id[idx];

    __shared__ u64 sp[256];
    sp[tid] = pack_vi(v, idx);
    __syncthreads();

    u64 mine = sp[tid];
    int rank = 0;
#pragma unroll
    for (int j = 0; j < NCAND; j++) rank += (sp[rloc * 16 + j] > mine);
    if (rank < KTOP) {
        float cc = fminf(fmaxf(v, -1.0f), 1.0f);
        out[(size_t)row * KTOP + rank] = acosf(cc);
        out[(size_t)NEXP * KTOP + (size_t)row * KTOP + rank] = (float)idx;
        const float* qt = so3 + (size_t)idx * 4;
        float* od = out + 2 * (size_t)NEXP * KTOP + ((size_t)row * KTOP + rank) * 4;
        od[0] = qt[0]; od[1] = qt[1]; od[2] = qt[2]; od[3] = qt[3];
    }
}

extern "C" void kernel_launch(void* const* d_in, const int* in_sizes, int n_in,
                              void* d_out, int out_size) {
    const float* Q   = (const float*)d_in[0];
    const float* P   = (const float*)d_in[1];
    const float* SO3 = (const float*)d_in[2];
    float* out = (float*)d_out;

    cudaFuncSetAttribute(gemm_kernel, cudaFuncAttributeMaxDynamicSharedMemorySize, SMEM_DYN);

    // gemm sits in the 4th (ncu-captured) launch slot.
    convert_kernel<<<NEXP / 2, 512>>>(Q, 0, 0);
    convert_kernel<<<NDICT / 4, 512>>>(P, 1, 0);
    convert_kernel<<<NDICT / 4, 512>>>(P, 1, NDICT / 2);

    dim3 grid(NEXP / BM, NDICT / BN);  // (16, 512)
    gemm_kernel<<<grid, 256, SMEM_DYN>>>();

    merge16_kernel<<<NEXP, 256>>>();
    rescore_kernel<<<NEXP / 16, 256>>>(Q, P, SO3, out);
}

// round 16
// speedup vs baseline: 1.3082x; 1.1776x over previous
#include <cuda_runtime.h>
#include <cuda_fp16.h>
#include <cstdint>

#define NEXP 2048
#define NDICT 65536
#define NPIX 1600
#define ROWB 3200              // NPIX * 2 bytes per f16 row == exactly 25x128B
#define KTOP 10
#define KTILE 5                // candidates kept per (row, 128-col tile)
#define NCAND 16
#define BM 128
#define BN 128
#define NST 25                 // k-stages of 64 f16 values (128B per row)
#define NTILE (NDICT / BN)     // 512 candidate tiles per row
#define STAGE_BYTES 32768      // A:128*128B + B:128*128B
#define SMEM_DYN (3 * STAGE_BYTES)

typedef unsigned long long u64;

__device__ __half g_Qs[(size_t)NEXP * NPIX];   // hi-f16, row-major (unpadded)
__device__ __half g_Ps[(size_t)NDICT * NPIX];
__device__ float g_mq[NEXP], g_iq[NEXP], g_md[NDICT], g_id[NDICT];
__device__ u64 g_cand[(size_t)NEXP * NTILE * KTILE];   // 42 MB
__device__ int g_top16[(size_t)NEXP * NCAND];

__device__ __forceinline__ uint32_t s2u(const void* p) {
    uint32_t a;
    asm("{ .reg .u64 t; cvta.to.shared.u64 t, %1; cvt.u32.u64 %0, t; }" : "=r"(a) : "l"(p));
    return a;
}
#define LDSM4(r, addr) asm volatile( \
    "ldmatrix.sync.aligned.m8n8.x4.shared.b16 {%0,%1,%2,%3}, [%4];" \
    : "=r"((r)[0]), "=r"((r)[1]), "=r"((r)[2]), "=r"((r)[3]) : "r"(addr))
#define MMA(d, a, b0, b1) asm volatile( \
    "mma.sync.aligned.m16n8k16.row.col.f32.f16.f16.f32 " \
    "{%0,%1,%2,%3},{%4,%5,%6,%7},{%8,%9},{%0,%1,%2,%3};" \
    : "+f"((d)[0]), "+f"((d)[1]), "+f"((d)[2]), "+f"((d)[3]) \
    : "r"((a)[0]), "r"((a)[1]), "r"((a)[2]), "r"((a)[3]), "r"(b0), "r"(b1))
#define CPA16(dst, src) asm volatile( \
    "cp.async.cg.shared.global [%0], [%1], 16;" :: "r"(dst), "l"(src) : "memory")

__device__ __forceinline__ u64 pack_vi(float v, int idx) {
    uint32_t ub = __float_as_uint(v);
    ub = (ub & 0x80000000u) ? ~ub : (ub | 0x80000000u);
    return ((u64)ub << 32) | (uint32_t)(~(uint32_t)idx);
}
template <int K>
__device__ __forceinline__ void insK(u64* top, u64 p) {
    if (p > top[K - 1]) {
#pragma unroll
        for (int q = K - 1; q >= 1; q--)
            if (top[q - 1] < p) top[q] = top[q - 1];
        bool placed = false;
#pragma unroll
        for (int q = 0; q < K; q++)
            if (!placed && top[q] < p) { top[q] = p; placed = true; }
    }
}

// fp32 -> hi-f16 + row stats. Per-row stats arithmetic is bitwise identical
// to the R1 rowstats kernel (same loop/shuffle/final-sum).
__global__ void __launch_bounds__(512, 2)
convert_kernel(const float* __restrict__ X, int which, int rbase) {
    const int half = threadIdx.x >> 8, tid = threadIdx.x & 255;
    const int row = rbase + blockIdx.x * 2 + half;
    const float* x = X + (size_t)row * NPIX;
    __half* o = (which ? g_Ps : g_Qs) + (size_t)row * NPIX;
    float s = 0.f, s2 = 0.f;
    for (int i = tid; i < NPIX; i += 256) {
        float f = x[i];
        s += f; s2 += f * f;
        o[i] = __float2half_rn(f);
    }
#pragma unroll
    for (int off = 16; off > 0; off >>= 1) {
        s  += __shfl_down_sync(0xffffffffu, s, off);
        s2 += __shfl_down_sync(0xffffffffu, s2, off);
    }
    __shared__ float sh_s[2][8], sh_s2[2][8];
    int w = tid >> 5, l = tid & 31;
    if (l == 0) { sh_s[half][w] = s; sh_s2[half][w] = s2; }
    __syncthreads();
    if (tid == 0) {
        float ts = 0.f, ts2 = 0.f;
#pragma unroll
        for (int i = 0; i < 8; i++) { ts += sh_s[half][i]; ts2 += sh_s2[half][i]; }
        float m = ts / (float)NPIX;
        float inv = rsqrtf(ts2 - m * ts);
        if (which) { g_md[row] = m; g_id[row] = inv; }
        else       { g_mq[row] = m; g_iq[row] = inv; }
    }
}

// 1-term hi-f16 selection GEMM (R10/R15 winner config).
// CTA 128x128, 256 threads, 8 warps of 32x64, 3-stage cp.async, 2 CTAs/SM.
__global__ void __launch_bounds__(256, 2) gemm_kernel() {
    extern __shared__ uint8_t dsm[];
    __shared__ float2 s_nd[BN];

    const int tid = threadIdx.x, lane = tid & 31, wid = tid >> 5;
    const int wm = wid & 3, wn = wid >> 2;       // 4 x 2 warps of 32x64
    const int m_base = blockIdx.x * BM, n_base = blockIdx.y * BN;
    const uint32_t sbase = s2u(dsm);

    // ---- producer constants: 8 x 16B cp.async per thread per stage ----
    const int r0 = tid >> 3;
    const uint32_t s8 = (uint32_t)(tid & 7);
    const uint32_t sw = ((uint32_t)(r0 & 7)) << 4;   // row&7 invariant over jj
    const uint32_t dst0 = (uint32_t)r0 * 128u + ((s8 * 16u) ^ sw);
    const char* srcA0 = (const char*)g_Qs + (size_t)(m_base + r0) * ROWB + s8 * 16u;
    const char* srcB0 = (const char*)g_Ps + (size_t)(n_base + r0) * ROWB + s8 * 16u;

    // ---- ldmatrix lane constants (SW128), hoisted per k-step ----
    const uint32_t xorL  = (uint32_t)(lane & 7) << 4;
    const uint32_t halfA = (uint32_t)(lane >> 4) << 4;
    const uint32_t halfB = (uint32_t)((lane >> 3) & 1) << 4;
    const uint32_t aoff0 = (uint32_t)(32 * wm + (lane & 15)) * 128u;
    const uint32_t aoff1 = aoff0 + 16 * 128u;
    uint32_t boff[4];
#pragma unroll
    for (int j = 0; j < 4; j++)
        boff[j] = 16384u + (uint32_t)(64 * wn + 16 * j + (lane & 7) + 8 * ((lane >> 4) & 1)) * 128u;
    uint32_t lowA[4], lowB[4];
#pragma unroll
    for (int s = 0; s < 4; s++) {
        lowA[s] = ((32u * s) | halfA) ^ xorL;
        lowB[s] = ((32u * s) | halfB) ^ xorL;
    }

    float acc[2][8][4];
#pragma unroll
    for (int i = 0; i < 2; i++)
#pragma unroll
        for (int j = 0; j < 8; j++)
#pragma unroll
            for (int k = 0; k < 4; k++) acc[i][j][k] = 0.f;

    // ---- prologue: stages 0,1 ----
#pragma unroll
    for (int p = 0; p < 2; p++) {
        const uint32_t sb = sbase + p * STAGE_BYTES;
#pragma unroll
        for (int jj = 0; jj < 4; jj++) {
            CPA16(sb + dst0 + 4096u * jj, srcA0 + (size_t)p * 128 + (size_t)jj * (32 * ROWB));
            CPA16(sb + 16384u + dst0 + 4096u * jj,
                  srcB0 + (size_t)p * 128 + (size_t)jj * (32 * ROWB));
        }
        asm volatile("cp.async.commit_group;" ::: "memory");
    }

    for (int t = 0; t < NST; t++) {
        asm volatile("cp.async.wait_group 1;" ::: "memory");
        __syncthreads();
        if (t + 2 < NST) {
            const uint32_t sb = sbase + ((t + 2) % 3) * STAGE_BYTES;
            const size_t ko = (size_t)(t + 2) * 128;
#pragma unroll
            for (int jj = 0; jj < 4; jj++) {
                CPA16(sb + dst0 + 4096u * jj, srcA0 + ko + (size_t)jj * (32 * ROWB));
                CPA16(sb + 16384u + dst0 + 4096u * jj, srcB0 + ko + (size_t)jj * (32 * ROWB));
            }
        }
        asm volatile("cp.async.commit_group;" ::: "memory");

        const uint32_t sb = sbase + (t % 3) * STAGE_BYTES;
#pragma unroll
        for (int s = 0; s < 4; s++) {          // 4 k16-steps per 128B stage
            uint32_t a0[4], a1[4];
            LDSM4(a0, sb + aoff0 + lowA[s]);
            LDSM4(a1, sb + aoff1 + lowA[s]);
#pragma unroll
            for (int j = 0; j < 4; j++) {
                uint32_t b[4];
                LDSM4(b, sb + boff[j] + lowB[s]);
                MMA(acc[0][2 * j],     a0, b[0], b[1]);
                MMA(acc[0][2 * j + 1], a0, b[2], b[3]);
                MMA(acc[1][2 * j],     a1, b[0], b[1]);
                MMA(acc[1][2 * j + 1], a1, b[2], b[3]);
            }
        }
    }
    __syncthreads();

    // ---- epilogue: dump C tile to smem (128 x 136 f32 = 70KB) ----
    float* cbuf = (float*)dsm;
#pragma unroll
    for (int mi = 0; mi < 2; mi++)
#pragma unroll
        for (int nf = 0; nf < 8; nf++) {
            int r = 32 * wm + 16 * mi + (lane >> 2);
            int c = 64 * wn + 8 * nf + 2 * (lane & 3);
            cbuf[r * 136 + c]           = acc[mi][nf][0];
            cbuf[r * 136 + c + 1]       = acc[mi][nf][1];
            cbuf[(r + 8) * 136 + c]     = acc[mi][nf][2];
            cbuf[(r + 8) * 136 + c + 1] = acc[mi][nf][3];
        }
    if (tid < BN) {
        int n = n_base + tid;
        float idv = g_id[n];
        s_nd[tid] = make_float2(idv, g_md[n] * idv);
    }
    __syncthreads();

    // ---- per (row, 64-col chunk) top-5 ----
    const int row = tid >> 1, chunk = tid & 1;
    const int grow = m_base + row;
    const float iqv = g_iq[grow];
    const float cmq = (float)NPIX * g_mq[grow];
    u64 top[KTILE];
#pragma unroll
    for (int i = 0; i < KTILE; i++) top[i] = 0ULL;

    const int cb = 64 * chunk;
#pragma unroll 8
    for (int jj = 0; jj < 64; jj++) {
        int col = cb + jj;
        float2 nd = s_nd[col];
        float v = (cbuf[row * 136 + col] * nd.x - cmq * nd.y) * iqv;
        insK<KTILE>(top, pack_vi(v, n_base + col));
    }
    __syncthreads();   // all cbuf reads done; reuse smem for candidates

    u64* csm = (u64*)dsm;   // [256][KTILE] = 10 KB
#pragma unroll
    for (int i = 0; i < KTILE; i++) csm[tid * KTILE + i] = top[i];
    __syncthreads();

    // ---- 2->1 chunk merge per row, write one top-5 list per (row, tile) ----
    if (tid < BM) {
        u64 mtop[KTILE];
#pragma unroll
        for (int i = 0; i < KTILE; i++) mtop[i] = 0ULL;
        const u64* base = csm + (size_t)tid * 2 * KTILE;
        for (int c = 0; c < 2 * KTILE; c++) insK<KTILE>(mtop, base[c]);
        u64* dst = g_cand + ((size_t)(m_base + tid) * NTILE + blockIdx.y) * KTILE;
#pragma unroll
        for (int i = 0; i < KTILE; i++) dst[i] = mtop[i];
    }
}

// Merge 512 tile-lists per row -> top-16 candidate INDICES (selection only).
__global__ void merge16_kernel() {
    const int row = blockIdx.x, tid = threadIdx.x;  // 256 threads
    __shared__ u64 c[256 * KTOP];
    __shared__ u64 red[256];

    // local merge of this thread's 2 tile-lists (2*KTILE=10 items)
    u64 top[KTOP];
#pragma unroll
    for (int i = 0; i < KTOP; i++) top[i] = 0ULL;
    const u64* src = g_cand + ((size_t)row * NTILE + (size_t)tid * 2) * KTILE;
    for (int j = 0; j < 2 * KTILE; j++) insK<KTOP>(top, src[j]);
#pragma unroll
    for (int j = 0; j < KTOP; j++) c[tid * KTOP + j] = top[j];  // sorted desc
    int cur = 0;
    __syncthreads();

    for (int r = 0; r < NCAND; r++) {
        u64 v = (cur < KTOP) ? c[tid * KTOP + cur] : 0ULL;
        red[tid] = v;
        __syncthreads();
        for (int s = 128; s > 0; s >>= 1) {
            if (tid < s && red[tid + s] > red[tid]) red[tid] = red[tid + s];
            __syncthreads();
        }
        u64 w = red[0];
        if (v == w && cur < KTOP) cur++;
        if (tid == 0)
            g_top16[(size_t)row * NCAND + r] = (int)(~(uint32_t)(w & 0xffffffffu));
        __syncthreads();
    }
}

// EXACT rescore (bitwise-replicates the R1 kernel's accumulation order):
// one thread per candidate, single fp32 fmaf chain over k ascending on RAW
// inputs + R1's exact epilogue. Reproduces reference-observed ordering.
__global__ void __launch_bounds__(256, 4)
rescore_kernel(const float* __restrict__ Q, const float* __restrict__ P,
               const float* __restrict__ so3, float* __restrict__ out) {
    const int tid = threadIdx.x;
    const int rloc = tid >> 4, cand = tid & 15;
    const int row = blockIdx.x * 16 + rloc;
    const int idx = g_top16[(size_t)row * NCAND + cand];

    const float* q = Q + (size_t)row * NPIX;
    const float* p = P + (size_t)idx * NPIX;
    float acc = 0.f;
#pragma unroll 8
    for (int k = 0; k < NPIX; k++)
        acc = fmaf(q[k], p[k], acc);

    float corr = (float)NPIX * g_mq[row];
    float v = (acc - corr * g_md[idx]) * g_iq[row] * g_id[idx];

    __shared__ u64 sp[256];
    sp[tid] = pack_vi(v, idx);
    __syncthreads();

    u64 mine = sp[tid];
    int rank = 0;
#pragma unroll
    for (int j = 0; j < NCAND; j++) rank += (sp[rloc * 16 + j] > mine);
    if (rank < KTOP) {
        float cc = fminf(fmaxf(v, -1.0f), 1.0f);
        out[(size_t)row * KTOP + rank] = acosf(cc);
        out[(size_t)NEXP * KTOP + (size_t)row * KTOP + rank] = (float)idx;
        const float* qt = so3 + (size_t)idx * 4;
        float* od = out + 2 * (size_t)NEXP * KTOP + ((size_t)row * KTOP + rank) * 4;
        od[0] = qt[0]; od[1] = qt[1]; od[2] = qt[2]; od[3] = qt[3];
    }
}

extern "C" void kernel_launch(void* const* d_in, const int* in_sizes, int n_in,
                              void* d_out, int out_size) {
    const float* Q   = (const float*)d_in[0];
    const float* P   = (const float*)d_in[1];
    const float* SO3 = (const float*)d_in[2];
    float* out = (float*)d_out;

    cudaFuncSetAttribute(gemm_kernel, cudaFuncAttributeMaxDynamicSharedMemorySize, SMEM_DYN);

    // gemm sits in the 4th (ncu-captured) launch slot.
    convert_kernel<<<NEXP / 2, 512>>>(Q, 0, 0);
    convert_kernel<<<NDICT / 4, 512>>>(P, 1, 0);
    convert_kernel<<<NDICT / 4, 512>>>(P, 1, NDICT / 2);

    dim3 grid(NEXP / BM, NDICT / BN);  // (16, 512)
    gemm_kernel<<<grid, 256, SMEM_DYN>>>();

    merge16_kernel<<<NEXP, 256>>>();
    rescore_kernel<<<NEXP / 16, 256>>>(Q, P, SO3, out);
}